// round 8
// baseline (speedup 1.0000x reference)
#include <cuda_runtime.h>
#include <cstddef>
#include <cstdint>

// Problem constants
#define BB     16
#define CC     512
#define NN     1024      // H*W = 32*32
#define GROUPS 32
#define CPG    16        // channels per group
#define HEADS  8
#define CH     64        // channels per head

// Scratch (device globals — no allocation allowed)
__device__ float g_xn [(size_t)BB * CC * NN];        // 32 MB  groupnorm output
__device__ float g_qkv[(size_t)BB * 3 * CC * NN];    // 96 MB  qkv projection
__device__ float g_h  [(size_t)BB * CC * NN];        // 32 MB  attention output

// ---------------------------------------------------------------------------
// f32x2 packed-FMA helpers (sm_103a FFMA2 — only reachable via PTX)
// ---------------------------------------------------------------------------
__device__ __forceinline__ unsigned long long pack2(float lo, float hi) {
    unsigned long long r;
    asm("mov.b64 %0, {%1, %2};" : "=l"(r) : "f"(lo), "f"(hi));
    return r;
}
__device__ __forceinline__ void unpack2(unsigned long long v, float& lo, float& hi) {
    asm("mov.b64 {%0, %1}, %2;" : "=f"(lo), "=f"(hi) : "l"(v));
}
__device__ __forceinline__ void ffma2(unsigned long long& d,
                                      unsigned long long a,
                                      unsigned long long b) {
    asm("fma.rn.f32x2 %0, %1, %2, %0;" : "+l"(d) : "l"(a), "l"(b));
}

// cp.async helpers
__device__ __forceinline__ void cp_async16(void* smem_dst, const void* gsrc) {
    uint32_t sa = (uint32_t)__cvta_generic_to_shared(smem_dst);
    asm volatile("cp.async.cg.shared.global [%0], [%1], 16;" :: "r"(sa), "l"(gsrc));
}
__device__ __forceinline__ void cp_commit() {
    asm volatile("cp.async.commit_group;");
}
__device__ __forceinline__ void cp_wait0() {
    asm volatile("cp.async.wait_group 0;" ::: "memory");
}

// ---------------------------------------------------------------------------
// Kernel 1: GroupNorm.  One block per (batch, group). 16 ch * 1024 = 16384 el.
// ---------------------------------------------------------------------------
__global__ __launch_bounds__(256) void groupnorm_kernel(
    const float* __restrict__ x,
    const float* __restrict__ gamma,
    const float* __restrict__ beta,
    float* __restrict__ out)
{
    int bg = blockIdx.x;                 // 0..511
    int b  = bg / GROUPS;
    int g  = bg % GROUPS;
    const float* xp = x   + ((size_t)b * CC + (size_t)g * CPG) * NN;
    float*       op = out + ((size_t)b * CC + (size_t)g * CPG) * NN;
    int tid = threadIdx.x;

    float4 v[16];
    float s = 0.f, s2 = 0.f;
#pragma unroll
    for (int i = 0; i < 16; i++) {
        v[i] = ((const float4*)xp)[tid + i * 256];
        s  += v[i].x + v[i].y + v[i].z + v[i].w;
        s2 += v[i].x * v[i].x + v[i].y * v[i].y + v[i].z * v[i].z + v[i].w * v[i].w;
    }

    __shared__ float rs[256], rq[256];
    rs[tid] = s; rq[tid] = s2;
    __syncthreads();
    for (int off = 128; off > 0; off >>= 1) {
        if (tid < off) { rs[tid] += rs[tid + off]; rq[tid] += rq[tid + off]; }
        __syncthreads();
    }
    float mean = rs[0] * (1.0f / 16384.0f);
    float var  = rq[0] * (1.0f / 16384.0f) - mean * mean;
    float rstd = rsqrtf(var + 1e-5f);

#pragma unroll
    for (int i = 0; i < 16; i++) {
        int idx4 = tid + i * 256;
        int c_local = (idx4 * 4) >> 10;
        float gm = gamma[g * CPG + c_local] * rstd;
        float bt = beta [g * CPG + c_local] - mean * gm;
        float4 o;
        o.x = v[i].x * gm + bt;
        o.y = v[i].y * gm + bt;
        o.z = v[i].z * gm + bt;
        o.w = v[i].w * gm + bt;
        ((float4*)op)[idx4] = o;
    }
}

// ---------------------------------------------------------------------------
// Kernel 2/4: batched SGEMM with packed f32x2 microkernel.
// C[b] = A(MxK) @ B[b](KxN) + bias (+ residual)
// 128x128 tile, Ktile=8, double-buffered smem, 8x8 microtile (as 8x4 f32x2).
// ---------------------------------------------------------------------------
__global__ __launch_bounds__(256) void gemm_kernel(
    const float* __restrict__ A,
    const float* __restrict__ Bm,
    const float* __restrict__ bias,
    const float* __restrict__ res,
    float* __restrict__ Cm,
    int M, int K, int N)
{
    __shared__ __align__(16) float As[2][8][128];
    __shared__ __align__(16) float Bs[2][8][128];

    int bz = blockIdx.z;
    const float* Bp = Bm + (size_t)bz * K * N;
    float*       Cp = Cm + (size_t)bz * M * N;

    int tid = threadIdx.x;
    int m0 = blockIdx.y * 128;
    int n0 = blockIdx.x * 128;

    int a_row = tid >> 1;
    int a_k4  = (tid & 1) * 4;
    int b_row = tid >> 5;
    int b_col = (tid & 31) * 4;

    float4 a_frag = *(const float4*)(A  + (size_t)(m0 + a_row) * K + a_k4);
    float4 b_frag = *(const float4*)(Bp + (size_t)b_row * N + n0 + b_col);
    As[0][a_k4 + 0][a_row] = a_frag.x;
    As[0][a_k4 + 1][a_row] = a_frag.y;
    As[0][a_k4 + 2][a_row] = a_frag.z;
    As[0][a_k4 + 3][a_row] = a_frag.w;
    *(float4*)&Bs[0][b_row][b_col] = b_frag;
    __syncthreads();

    unsigned long long acc2[8][4];
#pragma unroll
    for (int i = 0; i < 8; i++)
#pragma unroll
        for (int j = 0; j < 4; j++) acc2[i][j] = 0ULL;

    int tx = tid & 15;   // n
    int ty = tid >> 4;   // m
    int KT = K >> 3;

    for (int kt = 0; kt < KT; ++kt) {
        int buf = kt & 1;
        if (kt + 1 < KT) {
            int kg = (kt + 1) * 8;
            a_frag = *(const float4*)(A  + (size_t)(m0 + a_row) * K + kg + a_k4);
            b_frag = *(const float4*)(Bp + (size_t)(kg + b_row) * N + n0 + b_col);
        }
#pragma unroll
        for (int k = 0; k < 8; k++) {
            float4 a0 = *(const float4*)&As[buf][k][ty * 4];
            float4 a1 = *(const float4*)&As[buf][k][ty * 4 + 64];
            ulonglong2 b0 = *(const ulonglong2*)&Bs[buf][k][tx * 4];
            ulonglong2 b1 = *(const ulonglong2*)&Bs[buf][k][tx * 4 + 64];
            unsigned long long am[8];
            am[0] = pack2(a0.x, a0.x); am[1] = pack2(a0.y, a0.y);
            am[2] = pack2(a0.z, a0.z); am[3] = pack2(a0.w, a0.w);
            am[4] = pack2(a1.x, a1.x); am[5] = pack2(a1.y, a1.y);
            am[6] = pack2(a1.z, a1.z); am[7] = pack2(a1.w, a1.w);
#pragma unroll
            for (int i = 0; i < 8; i++) {
                ffma2(acc2[i][0], am[i], b0.x);
                ffma2(acc2[i][1], am[i], b0.y);
                ffma2(acc2[i][2], am[i], b1.x);
                ffma2(acc2[i][3], am[i], b1.y);
            }
        }
        if (kt + 1 < KT) {
            int nbuf = (kt + 1) & 1;
            As[nbuf][a_k4 + 0][a_row] = a_frag.x;
            As[nbuf][a_k4 + 1][a_row] = a_frag.y;
            As[nbuf][a_k4 + 2][a_row] = a_frag.z;
            As[nbuf][a_k4 + 3][a_row] = a_frag.w;
            *(float4*)&Bs[nbuf][b_row][b_col] = b_frag;
            __syncthreads();
        }
    }

    // epilogue
#pragma unroll
    for (int i = 0; i < 8; i++) {
        int m = m0 + ((i < 4) ? (ty * 4 + i) : (64 + ty * 4 + (i - 4)));
        float bv = bias[m];
#pragma unroll
        for (int jh = 0; jh < 2; jh++) {
            int n = n0 + jh * 64 + tx * 4;
            float x0, x1, x2, x3;
            unpack2(acc2[i][jh * 2 + 0], x0, x1);
            unpack2(acc2[i][jh * 2 + 1], x2, x3);
            float4 r;
            r.x = x0 + bv; r.y = x1 + bv; r.z = x2 + bv; r.w = x3 + bv;
            if (res != nullptr) {
                float4 rv = *(const float4*)(res + (size_t)bz * M * N + (size_t)m * N + n);
                r.x += rv.x; r.y += rv.y; r.z += rv.z; r.w += rv.w;
            }
            *(float4*)(Cp + (size_t)m * N + n) = r;
        }
    }
}

// ---------------------------------------------------------------------------
// Kernel 3: flash attention, v2 (FIXED row-stride indexing).
// grid = (8 t-tiles, 128 heads), 128 threads, 2 blocks/SM.
// Thread owns one t-row. S row kept in REGISTERS as 32 packed f32x2 (64 j's).
// K/V tiles stored [c][j] (conflict-free writes, broadcast reads), Bc = 64,
// cp.async double-buffered. q in smem (self-read only, no sync needed).
// A tile row (64 floats) = 16 ulonglong2: row stride 16, j8 in [0,16).
// smem: Ks 2*16KB + Vs 2*16KB + Qs 32KB = 96KB  -> 2 blocks/SM (8 warps).
// ---------------------------------------------------------------------------
#define BC 64
#define ATTN_SMEM_FLOATS (2 * 4096 + 2 * 4096 + 64 * 128)
#define ATTN_SMEM_BYTES  (ATTN_SMEM_FLOATS * 4)

__global__ __launch_bounds__(128, 2) void attn_kernel(
    const float* __restrict__ qkv,
    float* __restrict__ hout)
{
    extern __shared__ float sm[];
    float* Ks = sm;                  // [2][64c][64j]
    float* Vs = sm + 2 * 4096;       // [2][64c][64j]
    float* Qs = sm + 4 * 4096;       // [64c][128t]

    int tt   = blockIdx.x;           // 0..7
    int head = blockIdx.y;           // 0..127
    int b  = head >> 3;
    int hl = head & 7;
    const float* base = qkv + ((size_t)b * 1536 + (size_t)hl * 192) * NN;
    const float* qg = base;
    const float* kg = base + 64 * NN;
    const float* vg = base + 128 * NN;

    int tid = threadIdx.x;
    int t = tt * 128 + tid;

    // q -> smem (scaled). Read back only by the same thread: no sync needed.
    for (int c = 0; c < CH; c++)
        Qs[c * 128 + tid] = qg[(size_t)c * NN + t] * 0.125f;

    // cp.async tile loader: [c][j] layout, 16B chunks, coalesced gmem reads
    int jj    = (tid & 15) * 4;      // j offset 0..60
    int chalf = tid >> 4;            // 0..7

    // prologue: tile 0 into buf 0
    {
#pragma unroll
        for (int p = 0; p < 8; p++) {
            int c = p * 8 + chalf;
            cp_async16(Ks + c * 64 + jj, kg + (size_t)c * NN + jj);
            cp_async16(Vs + c * 64 + jj, vg + (size_t)c * NN + jj);
        }
        cp_commit();
    }

    float o[CH];
#pragma unroll
    for (int c = 0; c < CH; c++) o[c] = 0.f;
    float mrun = -1e30f, lrun = 0.f;

    for (int st = 0; st < 16; ++st) {
        int buf = st & 1;
        cp_wait0();            // this tile's data landed (this thread's part)
        __syncthreads();       // all threads' parts landed; prev compute done

        if (st < 15) {         // prefetch next tile into the other buffer
            int s0n = (st + 1) * BC;
            float* Kb = Ks + (buf ^ 1) * 4096;
            float* Vb = Vs + (buf ^ 1) * 4096;
#pragma unroll
            for (int p = 0; p < 8; p++) {
                int c = p * 8 + chalf;
                cp_async16(Kb + c * 64 + jj, kg + (size_t)c * NN + s0n + jj);
                cp_async16(Vb + c * 64 + jj, vg + (size_t)c * NN + s0n + jj);
            }
            cp_commit();
        }

        // ---- S = q . K  (32 packed-pair accumulators = 64 scores) ----
        unsigned long long s2[32];
#pragma unroll
        for (int i = 0; i < 32; i++) s2[i] = 0ULL;

        const ulonglong2* K2 = (const ulonglong2*)(Ks + buf * 4096);
#pragma unroll
        for (int c = 0; c < CH; c++) {
            float qc = Qs[c * 128 + tid];
            unsigned long long qq = pack2(qc, qc);
#pragma unroll
            for (int j8 = 0; j8 < 16; j8++) {          // 16 x ulonglong2 = 64 j
                ulonglong2 kk = K2[c * 16 + j8];       // row stride 16
                ffma2(s2[2 * j8 + 0], qq, kk.x);
                ffma2(s2[2 * j8 + 1], qq, kk.y);
            }
        }

        // ---- online softmax ----
        float m0 = -1e30f, m1 = -1e30f, m2 = -1e30f, m3 = -1e30f;
#pragma unroll
        for (int i = 0; i < 32; i += 2) {
            float a, bb, cc, dd;
            unpack2(s2[i], a, bb);
            unpack2(s2[i + 1], cc, dd);
            m0 = fmaxf(m0, a); m1 = fmaxf(m1, bb);
            m2 = fmaxf(m2, cc); m3 = fmaxf(m3, dd);
        }
        float tmax = fmaxf(fmaxf(m0, m1), fmaxf(m2, m3));
        float mnew = fmaxf(mrun, tmax);
        float corr = __expf(mrun - mnew);
#pragma unroll
        for (int c = 0; c < CH; c++) o[c] *= corr;

        float l0 = 0.f, l1 = 0.f;
#pragma unroll
        for (int i = 0; i < 32; i++) {
            float a, bb;
            unpack2(s2[i], a, bb);
            a = __expf(a - mnew);
            bb = __expf(bb - mnew);
            l0 += a; l1 += bb;
            s2[i] = pack2(a, bb);
        }
        lrun = lrun * corr + l0 + l1;
        mrun = mnew;

        // ---- O += P . V^T ----
        const ulonglong2* V2 = (const ulonglong2*)(Vs + buf * 4096);
#pragma unroll
        for (int c = 0; c < CH; c++) {
            unsigned long long t0 = 0ULL, t1 = 0ULL;
#pragma unroll
            for (int j8 = 0; j8 < 16; j8++) {          // full 64-j row
                ulonglong2 vv = V2[c * 16 + j8];       // row stride 16
                ffma2(t0, s2[2 * j8 + 0], vv.x);
                ffma2(t1, s2[2 * j8 + 1], vv.y);
            }
            float a, bb, cc, dd;
            unpack2(t0, a, bb);
            unpack2(t1, cc, dd);
            o[c] += (a + bb) + (cc + dd);
        }
        // no trailing sync needed: next iteration's top sync (after cp_wait0)
        // orders this compute before any overwrite of this buffer.
    }

    float inv = 1.0f / lrun;
    float* hp = hout + ((size_t)b * CC + (size_t)hl * CH) * NN;
#pragma unroll
    for (int c = 0; c < CH; c++) hp[(size_t)c * NN + t] = o[c] * inv;
}

// ---------------------------------------------------------------------------
// Launch
// ---------------------------------------------------------------------------
extern "C" void kernel_launch(void* const* d_in, const int* in_sizes, int n_in,
                              void* d_out, int out_size)
{
    const float* x      = (const float*)d_in[0];
    const float* gamma  = (const float*)d_in[1];
    const float* beta   = (const float*)d_in[2];
    const float* w_qkv  = (const float*)d_in[3];
    const float* b_qkv  = (const float*)d_in[4];
    const float* w_proj = (const float*)d_in[5];
    const float* b_proj = (const float*)d_in[6];
    float* out = (float*)d_out;

    float *xn, *qkv, *h;
    cudaGetSymbolAddress((void**)&xn,  g_xn);
    cudaGetSymbolAddress((void**)&qkv, g_qkv);
    cudaGetSymbolAddress((void**)&h,   g_h);

    // 1. GroupNorm
    groupnorm_kernel<<<BB * GROUPS, 256>>>(x, gamma, beta, xn);

    // 2. QKV projection: (1536,512) @ (16,512,1024) + bias
    gemm_kernel<<<dim3(NN / 128, (3 * CC) / 128, BB), 256>>>(
        w_qkv, xn, b_qkv, nullptr, qkv, 3 * CC, CC, NN);

    // 3. Attention
    cudaFuncSetAttribute(attn_kernel, cudaFuncAttributeMaxDynamicSharedMemorySize,
                         ATTN_SMEM_BYTES);
    attn_kernel<<<dim3(8, BB * HEADS), 128, ATTN_SMEM_BYTES>>>(qkv, h);

    // 4. Output projection + bias + residual
    gemm_kernel<<<dim3(NN / 128, CC / 128, BB), 256>>>(
        w_proj, h, b_proj, x, out, CC, CC, NN);
}

// round 9
// speedup vs baseline: 1.0017x; 1.0017x over previous
#include <cuda_runtime.h>
#include <cstddef>
#include <cstdint>

// Problem constants
#define BB     16
#define CC     512
#define NN     1024      // H*W = 32*32
#define GROUPS 32
#define CPG    16        // channels per group
#define HEADS  8
#define CH     64        // channels per head

// Scratch (device globals — no allocation allowed)
__device__ float g_xn [(size_t)BB * CC * NN];        // 32 MB  groupnorm output
__device__ float g_qkv[(size_t)BB * 3 * CC * NN];    // 96 MB  qkv projection
__device__ float g_h  [(size_t)BB * CC * NN];        // 32 MB  attention output

// ---------------------------------------------------------------------------
// f32x2 packed-FMA helpers (sm_103a FFMA2 — only reachable via PTX)
// ---------------------------------------------------------------------------
__device__ __forceinline__ unsigned long long pack2(float lo, float hi) {
    unsigned long long r;
    asm("mov.b64 %0, {%1, %2};" : "=l"(r) : "f"(lo), "f"(hi));
    return r;
}
__device__ __forceinline__ void unpack2(unsigned long long v, float& lo, float& hi) {
    asm("mov.b64 {%0, %1}, %2;" : "=f"(lo), "=f"(hi) : "l"(v));
}
__device__ __forceinline__ void ffma2(unsigned long long& d,
                                      unsigned long long a,
                                      unsigned long long b) {
    asm("fma.rn.f32x2 %0, %1, %2, %0;" : "+l"(d) : "l"(a), "l"(b));
}

// cp.async helpers
__device__ __forceinline__ void cp_async16(void* smem_dst, const void* gsrc) {
    uint32_t sa = (uint32_t)__cvta_generic_to_shared(smem_dst);
    asm volatile("cp.async.cg.shared.global [%0], [%1], 16;" :: "r"(sa), "l"(gsrc));
}
__device__ __forceinline__ void cp_commit() {
    asm volatile("cp.async.commit_group;");
}
__device__ __forceinline__ void cp_wait0() {
    asm volatile("cp.async.wait_group 0;" ::: "memory");
}

// ---------------------------------------------------------------------------
// Kernel 1: GroupNorm.  One block per (batch, group). 16 ch * 1024 = 16384 el.
// ---------------------------------------------------------------------------
__global__ __launch_bounds__(256) void groupnorm_kernel(
    const float* __restrict__ x,
    const float* __restrict__ gamma,
    const float* __restrict__ beta,
    float* __restrict__ out)
{
    int bg = blockIdx.x;                 // 0..511
    int b  = bg / GROUPS;
    int g  = bg % GROUPS;
    const float* xp = x   + ((size_t)b * CC + (size_t)g * CPG) * NN;
    float*       op = out + ((size_t)b * CC + (size_t)g * CPG) * NN;
    int tid = threadIdx.x;

    float4 v[16];
    float s = 0.f, s2 = 0.f;
#pragma unroll
    for (int i = 0; i < 16; i++) {
        v[i] = ((const float4*)xp)[tid + i * 256];
        s  += v[i].x + v[i].y + v[i].z + v[i].w;
        s2 += v[i].x * v[i].x + v[i].y * v[i].y + v[i].z * v[i].z + v[i].w * v[i].w;
    }

    __shared__ float rs[256], rq[256];
    rs[tid] = s; rq[tid] = s2;
    __syncthreads();
    for (int off = 128; off > 0; off >>= 1) {
        if (tid < off) { rs[tid] += rs[tid + off]; rq[tid] += rq[tid + off]; }
        __syncthreads();
    }
    float mean = rs[0] * (1.0f / 16384.0f);
    float var  = rq[0] * (1.0f / 16384.0f) - mean * mean;
    float rstd = rsqrtf(var + 1e-5f);

#pragma unroll
    for (int i = 0; i < 16; i++) {
        int idx4 = tid + i * 256;
        int c_local = (idx4 * 4) >> 10;
        float gm = gamma[g * CPG + c_local] * rstd;
        float bt = beta [g * CPG + c_local] - mean * gm;
        float4 o;
        o.x = v[i].x * gm + bt;
        o.y = v[i].y * gm + bt;
        o.z = v[i].z * gm + bt;
        o.w = v[i].w * gm + bt;
        ((float4*)op)[idx4] = o;
    }
}

// ---------------------------------------------------------------------------
// Kernel 2/4: batched SGEMM with packed f32x2 microkernel.
// C[b] = A(MxK) @ B[b](KxN) + bias (+ residual)
// 128x128 tile, Ktile=8, double-buffered smem, 8x8 microtile (as 8x4 f32x2).
// ---------------------------------------------------------------------------
__global__ __launch_bounds__(256) void gemm_kernel(
    const float* __restrict__ A,
    const float* __restrict__ Bm,
    const float* __restrict__ bias,
    const float* __restrict__ res,
    float* __restrict__ Cm,
    int M, int K, int N)
{
    __shared__ __align__(16) float As[2][8][128];
    __shared__ __align__(16) float Bs[2][8][128];

    int bz = blockIdx.z;
    const float* Bp = Bm + (size_t)bz * K * N;
    float*       Cp = Cm + (size_t)bz * M * N;

    int tid = threadIdx.x;
    int m0 = blockIdx.y * 128;
    int n0 = blockIdx.x * 128;

    int a_row = tid >> 1;
    int a_k4  = (tid & 1) * 4;
    int b_row = tid >> 5;
    int b_col = (tid & 31) * 4;

    float4 a_frag = *(const float4*)(A  + (size_t)(m0 + a_row) * K + a_k4);
    float4 b_frag = *(const float4*)(Bp + (size_t)b_row * N + n0 + b_col);
    As[0][a_k4 + 0][a_row] = a_frag.x;
    As[0][a_k4 + 1][a_row] = a_frag.y;
    As[0][a_k4 + 2][a_row] = a_frag.z;
    As[0][a_k4 + 3][a_row] = a_frag.w;
    *(float4*)&Bs[0][b_row][b_col] = b_frag;
    __syncthreads();

    unsigned long long acc2[8][4];
#pragma unroll
    for (int i = 0; i < 8; i++)
#pragma unroll
        for (int j = 0; j < 4; j++) acc2[i][j] = 0ULL;

    int tx = tid & 15;   // n
    int ty = tid >> 4;   // m
    int KT = K >> 3;

    for (int kt = 0; kt < KT; ++kt) {
        int buf = kt & 1;
        if (kt + 1 < KT) {
            int kg = (kt + 1) * 8;
            a_frag = *(const float4*)(A  + (size_t)(m0 + a_row) * K + kg + a_k4);
            b_frag = *(const float4*)(Bp + (size_t)(kg + b_row) * N + n0 + b_col);
        }
#pragma unroll
        for (int k = 0; k < 8; k++) {
            float4 a0 = *(const float4*)&As[buf][k][ty * 4];
            float4 a1 = *(const float4*)&As[buf][k][ty * 4 + 64];
            ulonglong2 b0 = *(const ulonglong2*)&Bs[buf][k][tx * 4];
            ulonglong2 b1 = *(const ulonglong2*)&Bs[buf][k][tx * 4 + 64];
            unsigned long long am[8];
            am[0] = pack2(a0.x, a0.x); am[1] = pack2(a0.y, a0.y);
            am[2] = pack2(a0.z, a0.z); am[3] = pack2(a0.w, a0.w);
            am[4] = pack2(a1.x, a1.x); am[5] = pack2(a1.y, a1.y);
            am[6] = pack2(a1.z, a1.z); am[7] = pack2(a1.w, a1.w);
#pragma unroll
            for (int i = 0; i < 8; i++) {
                ffma2(acc2[i][0], am[i], b0.x);
                ffma2(acc2[i][1], am[i], b0.y);
                ffma2(acc2[i][2], am[i], b1.x);
                ffma2(acc2[i][3], am[i], b1.y);
            }
        }
        if (kt + 1 < KT) {
            int nbuf = (kt + 1) & 1;
            As[nbuf][a_k4 + 0][a_row] = a_frag.x;
            As[nbuf][a_k4 + 1][a_row] = a_frag.y;
            As[nbuf][a_k4 + 2][a_row] = a_frag.z;
            As[nbuf][a_k4 + 3][a_row] = a_frag.w;
            *(float4*)&Bs[nbuf][b_row][b_col] = b_frag;
            __syncthreads();
        }
    }

    // epilogue
#pragma unroll
    for (int i = 0; i < 8; i++) {
        int m = m0 + ((i < 4) ? (ty * 4 + i) : (64 + ty * 4 + (i - 4)));
        float bv = bias[m];
#pragma unroll
        for (int jh = 0; jh < 2; jh++) {
            int n = n0 + jh * 64 + tx * 4;
            float x0, x1, x2, x3;
            unpack2(acc2[i][jh * 2 + 0], x0, x1);
            unpack2(acc2[i][jh * 2 + 1], x2, x3);
            float4 r;
            r.x = x0 + bv; r.y = x1 + bv; r.z = x2 + bv; r.w = x3 + bv;
            if (res != nullptr) {
                float4 rv = *(const float4*)(res + (size_t)bz * M * N + (size_t)m * N + n);
                r.x += rv.x; r.y += rv.y; r.z += rv.z; r.w += rv.w;
            }
            *(float4*)(Cp + (size_t)m * N + n) = r;
        }
    }
}

// ---------------------------------------------------------------------------
// Kernel 3: flash attention, v2 (FIXED row-stride indexing).
// grid = (8 t-tiles, 128 heads), 128 threads, 2 blocks/SM.
// Thread owns one t-row. S row kept in REGISTERS as 32 packed f32x2 (64 j's).
// K/V tiles stored [c][j] (conflict-free writes, broadcast reads), Bc = 64,
// cp.async double-buffered. q in smem (self-read only, no sync needed).
// A tile row (64 floats) = 16 ulonglong2: row stride 16, j8 in [0,16).
// smem: Ks 2*16KB + Vs 2*16KB + Qs 32KB = 96KB  -> 2 blocks/SM (8 warps).
// ---------------------------------------------------------------------------
#define BC 64
#define ATTN_SMEM_FLOATS (2 * 4096 + 2 * 4096 + 64 * 128)
#define ATTN_SMEM_BYTES  (ATTN_SMEM_FLOATS * 4)

__global__ __launch_bounds__(128, 2) void attn_kernel(
    const float* __restrict__ qkv,
    float* __restrict__ hout)
{
    extern __shared__ float sm[];
    float* Ks = sm;                  // [2][64c][64j]
    float* Vs = sm + 2 * 4096;       // [2][64c][64j]
    float* Qs = sm + 4 * 4096;       // [64c][128t]

    int tt   = blockIdx.x;           // 0..7
    int head = blockIdx.y;           // 0..127
    int b  = head >> 3;
    int hl = head & 7;
    const float* base = qkv + ((size_t)b * 1536 + (size_t)hl * 192) * NN;
    const float* qg = base;
    const float* kg = base + 64 * NN;
    const float* vg = base + 128 * NN;

    int tid = threadIdx.x;
    int t = tt * 128 + tid;

    // q -> smem (scaled). Read back only by the same thread: no sync needed.
    for (int c = 0; c < CH; c++)
        Qs[c * 128 + tid] = qg[(size_t)c * NN + t] * 0.125f;

    // cp.async tile loader: [c][j] layout, 16B chunks, coalesced gmem reads
    int jj    = (tid & 15) * 4;      // j offset 0..60
    int chalf = tid >> 4;            // 0..7

    // prologue: tile 0 into buf 0
    {
#pragma unroll
        for (int p = 0; p < 8; p++) {
            int c = p * 8 + chalf;
            cp_async16(Ks + c * 64 + jj, kg + (size_t)c * NN + jj);
            cp_async16(Vs + c * 64 + jj, vg + (size_t)c * NN + jj);
        }
        cp_commit();
    }

    float o[CH];
#pragma unroll
    for (int c = 0; c < CH; c++) o[c] = 0.f;
    float mrun = -1e30f, lrun = 0.f;

    for (int st = 0; st < 16; ++st) {
        int buf = st & 1;
        cp_wait0();            // this tile's data landed (this thread's part)
        __syncthreads();       // all threads' parts landed; prev compute done

        if (st < 15) {         // prefetch next tile into the other buffer
            int s0n = (st + 1) * BC;
            float* Kb = Ks + (buf ^ 1) * 4096;
            float* Vb = Vs + (buf ^ 1) * 4096;
#pragma unroll
            for (int p = 0; p < 8; p++) {
                int c = p * 8 + chalf;
                cp_async16(Kb + c * 64 + jj, kg + (size_t)c * NN + s0n + jj);
                cp_async16(Vb + c * 64 + jj, vg + (size_t)c * NN + s0n + jj);
            }
            cp_commit();
        }

        // ---- S = q . K  (32 packed-pair accumulators = 64 scores) ----
        unsigned long long s2[32];
#pragma unroll
        for (int i = 0; i < 32; i++) s2[i] = 0ULL;

        const ulonglong2* K2 = (const ulonglong2*)(Ks + buf * 4096);
#pragma unroll
        for (int c = 0; c < CH; c++) {
            float qc = Qs[c * 128 + tid];
            unsigned long long qq = pack2(qc, qc);
#pragma unroll
            for (int j8 = 0; j8 < 16; j8++) {          // 16 x ulonglong2 = 64 j
                ulonglong2 kk = K2[c * 16 + j8];       // row stride 16
                ffma2(s2[2 * j8 + 0], qq, kk.x);
                ffma2(s2[2 * j8 + 1], qq, kk.y);
            }
        }

        // ---- online softmax ----
        float m0 = -1e30f, m1 = -1e30f, m2 = -1e30f, m3 = -1e30f;
#pragma unroll
        for (int i = 0; i < 32; i += 2) {
            float a, bb, cc, dd;
            unpack2(s2[i], a, bb);
            unpack2(s2[i + 1], cc, dd);
            m0 = fmaxf(m0, a); m1 = fmaxf(m1, bb);
            m2 = fmaxf(m2, cc); m3 = fmaxf(m3, dd);
        }
        float tmax = fmaxf(fmaxf(m0, m1), fmaxf(m2, m3));
        float mnew = fmaxf(mrun, tmax);
        float corr = __expf(mrun - mnew);
#pragma unroll
        for (int c = 0; c < CH; c++) o[c] *= corr;

        float l0 = 0.f, l1 = 0.f;
#pragma unroll
        for (int i = 0; i < 32; i++) {
            float a, bb;
            unpack2(s2[i], a, bb);
            a = __expf(a - mnew);
            bb = __expf(bb - mnew);
            l0 += a; l1 += bb;
            s2[i] = pack2(a, bb);
        }
        lrun = lrun * corr + l0 + l1;
        mrun = mnew;

        // ---- O += P . V^T ----
        const ulonglong2* V2 = (const ulonglong2*)(Vs + buf * 4096);
#pragma unroll
        for (int c = 0; c < CH; c++) {
            unsigned long long t0 = 0ULL, t1 = 0ULL;
#pragma unroll
            for (int j8 = 0; j8 < 16; j8++) {          // full 64-j row
                ulonglong2 vv = V2[c * 16 + j8];       // row stride 16
                ffma2(t0, s2[2 * j8 + 0], vv.x);
                ffma2(t1, s2[2 * j8 + 1], vv.y);
            }
            float a, bb, cc, dd;
            unpack2(t0, a, bb);
            unpack2(t1, cc, dd);
            o[c] += (a + bb) + (cc + dd);
        }
        // no trailing sync needed: next iteration's top sync (after cp_wait0)
        // orders this compute before any overwrite of this buffer.
    }

    float inv = 1.0f / lrun;
    float* hp = hout + ((size_t)b * CC + (size_t)hl * CH) * NN;
#pragma unroll
    for (int c = 0; c < CH; c++) hp[(size_t)c * NN + t] = o[c] * inv;
}

// ---------------------------------------------------------------------------
// Launch
// ---------------------------------------------------------------------------
extern "C" void kernel_launch(void* const* d_in, const int* in_sizes, int n_in,
                              void* d_out, int out_size)
{
    const float* x      = (const float*)d_in[0];
    const float* gamma  = (const float*)d_in[1];
    const float* beta   = (const float*)d_in[2];
    const float* w_qkv  = (const float*)d_in[3];
    const float* b_qkv  = (const float*)d_in[4];
    const float* w_proj = (const float*)d_in[5];
    const float* b_proj = (const float*)d_in[6];
    float* out = (float*)d_out;

    float *xn, *qkv, *h;
    cudaGetSymbolAddress((void**)&xn,  g_xn);
    cudaGetSymbolAddress((void**)&qkv, g_qkv);
    cudaGetSymbolAddress((void**)&h,   g_h);

    // 1. GroupNorm
    groupnorm_kernel<<<BB * GROUPS, 256>>>(x, gamma, beta, xn);

    // 2. QKV projection: (1536,512) @ (16,512,1024) + bias
    gemm_kernel<<<dim3(NN / 128, (3 * CC) / 128, BB), 256>>>(
        w_qkv, xn, b_qkv, nullptr, qkv, 3 * CC, CC, NN);

    // 3. Attention
    cudaFuncSetAttribute(attn_kernel, cudaFuncAttributeMaxDynamicSharedMemorySize,
                         ATTN_SMEM_BYTES);
    attn_kernel<<<dim3(8, BB * HEADS), 128, ATTN_SMEM_BYTES>>>(qkv, h);

    // 4. Output projection + bias + residual
    gemm_kernel<<<dim3(NN / 128, CC / 128, BB), 256>>>(
        w_proj, h, b_proj, x, out, CC, CC, NN);
}

// round 11
// speedup vs baseline: 1.0018x; 1.0001x over previous
#include <cuda_runtime.h>
#include <cstddef>
#include <cstdint>

// Problem constants
#define BB     16
#define CC     512
#define NN     1024      // H*W = 32*32
#define GROUPS 32
#define CPG    16        // channels per group
#define HEADS  8
#define CH     64        // channels per head

// Scratch (device globals — no allocation allowed)
__device__ float g_xn [(size_t)BB * CC * NN];        // 32 MB  groupnorm output
__device__ float g_qkv[(size_t)BB * 3 * CC * NN];    // 96 MB  qkv projection
__device__ float g_h  [(size_t)BB * CC * NN];        // 32 MB  attention output

// ---------------------------------------------------------------------------
// f32x2 packed-FMA helpers (sm_103a FFMA2 — only reachable via PTX)
// ---------------------------------------------------------------------------
__device__ __forceinline__ unsigned long long pack2(float lo, float hi) {
    unsigned long long r;
    asm("mov.b64 %0, {%1, %2};" : "=l"(r) : "f"(lo), "f"(hi));
    return r;
}
__device__ __forceinline__ void unpack2(unsigned long long v, float& lo, float& hi) {
    asm("mov.b64 {%0, %1}, %2;" : "=f"(lo), "=f"(hi) : "l"(v));
}
__device__ __forceinline__ void ffma2(unsigned long long& d,
                                      unsigned long long a,
                                      unsigned long long b) {
    asm("fma.rn.f32x2 %0, %1, %2, %0;" : "+l"(d) : "l"(a), "l"(b));
}

// cp.async helpers
__device__ __forceinline__ void cp_async16(void* smem_dst, const void* gsrc) {
    uint32_t sa = (uint32_t)__cvta_generic_to_shared(smem_dst);
    asm volatile("cp.async.cg.shared.global [%0], [%1], 16;" :: "r"(sa), "l"(gsrc));
}
__device__ __forceinline__ void cp_commit() {
    asm volatile("cp.async.commit_group;");
}
__device__ __forceinline__ void cp_wait0() {
    asm volatile("cp.async.wait_group 0;" ::: "memory");
}

// ---------------------------------------------------------------------------
// Kernel 1: GroupNorm.  One block per (batch, group). 16 ch * 1024 = 16384 el.
// ---------------------------------------------------------------------------
__global__ __launch_bounds__(256) void groupnorm_kernel(
    const float* __restrict__ x,
    const float* __restrict__ gamma,
    const float* __restrict__ beta,
    float* __restrict__ out)
{
    int bg = blockIdx.x;                 // 0..511
    int b  = bg / GROUPS;
    int g  = bg % GROUPS;
    const float* xp = x   + ((size_t)b * CC + (size_t)g * CPG) * NN;
    float*       op = out + ((size_t)b * CC + (size_t)g * CPG) * NN;
    int tid = threadIdx.x;

    float4 v[16];
    float s = 0.f, s2 = 0.f;
#pragma unroll
    for (int i = 0; i < 16; i++) {
        v[i] = ((const float4*)xp)[tid + i * 256];
        s  += v[i].x + v[i].y + v[i].z + v[i].w;
        s2 += v[i].x * v[i].x + v[i].y * v[i].y + v[i].z * v[i].z + v[i].w * v[i].w;
    }

    __shared__ float rs[256], rq[256];
    rs[tid] = s; rq[tid] = s2;
    __syncthreads();
    for (int off = 128; off > 0; off >>= 1) {
        if (tid < off) { rs[tid] += rs[tid + off]; rq[tid] += rq[tid + off]; }
        __syncthreads();
    }
    float mean = rs[0] * (1.0f / 16384.0f);
    float var  = rq[0] * (1.0f / 16384.0f) - mean * mean;
    float rstd = rsqrtf(var + 1e-5f);

#pragma unroll
    for (int i = 0; i < 16; i++) {
        int idx4 = tid + i * 256;
        int c_local = (idx4 * 4) >> 10;
        float gm = gamma[g * CPG + c_local] * rstd;
        float bt = beta [g * CPG + c_local] - mean * gm;
        float4 o;
        o.x = v[i].x * gm + bt;
        o.y = v[i].y * gm + bt;
        o.z = v[i].z * gm + bt;
        o.w = v[i].w * gm + bt;
        ((float4*)op)[idx4] = o;
    }
}

// ---------------------------------------------------------------------------
// Kernel 2/4: batched SGEMM with packed f32x2 microkernel.
// C[b] = A(MxK) @ B[b](KxN) + bias (+ residual)
// 128x128 tile, Ktile=8, double-buffered smem, 8x8 microtile (as 8x4 f32x2).
// ---------------------------------------------------------------------------
__global__ __launch_bounds__(256) void gemm_kernel(
    const float* __restrict__ A,
    const float* __restrict__ Bm,
    const float* __restrict__ bias,
    const float* __restrict__ res,
    float* __restrict__ Cm,
    int M, int K, int N)
{
    __shared__ __align__(16) float As[2][8][128];
    __shared__ __align__(16) float Bs[2][8][128];

    int bz = blockIdx.z;
    const float* Bp = Bm + (size_t)bz * K * N;
    float*       Cp = Cm + (size_t)bz * M * N;

    int tid = threadIdx.x;
    int m0 = blockIdx.y * 128;
    int n0 = blockIdx.x * 128;

    int a_row = tid >> 1;
    int a_k4  = (tid & 1) * 4;
    int b_row = tid >> 5;
    int b_col = (tid & 31) * 4;

    float4 a_frag = *(const float4*)(A  + (size_t)(m0 + a_row) * K + a_k4);
    float4 b_frag = *(const float4*)(Bp + (size_t)b_row * N + n0 + b_col);
    As[0][a_k4 + 0][a_row] = a_frag.x;
    As[0][a_k4 + 1][a_row] = a_frag.y;
    As[0][a_k4 + 2][a_row] = a_frag.z;
    As[0][a_k4 + 3][a_row] = a_frag.w;
    *(float4*)&Bs[0][b_row][b_col] = b_frag;
    __syncthreads();

    unsigned long long acc2[8][4];
#pragma unroll
    for (int i = 0; i < 8; i++)
#pragma unroll
        for (int j = 0; j < 4; j++) acc2[i][j] = 0ULL;

    int tx = tid & 15;   // n
    int ty = tid >> 4;   // m
    int KT = K >> 3;

    for (int kt = 0; kt < KT; ++kt) {
        int buf = kt & 1;
        if (kt + 1 < KT) {
            int kg = (kt + 1) * 8;
            a_frag = *(const float4*)(A  + (size_t)(m0 + a_row) * K + kg + a_k4);
            b_frag = *(const float4*)(Bp + (size_t)(kg + b_row) * N + n0 + b_col);
        }
#pragma unroll
        for (int k = 0; k < 8; k++) {
            float4 a0 = *(const float4*)&As[buf][k][ty * 4];
            float4 a1 = *(const float4*)&As[buf][k][ty * 4 + 64];
            ulonglong2 b0 = *(const ulonglong2*)&Bs[buf][k][tx * 4];
            ulonglong2 b1 = *(const ulonglong2*)&Bs[buf][k][tx * 4 + 64];
            unsigned long long am[8];
            am[0] = pack2(a0.x, a0.x); am[1] = pack2(a0.y, a0.y);
            am[2] = pack2(a0.z, a0.z); am[3] = pack2(a0.w, a0.w);
            am[4] = pack2(a1.x, a1.x); am[5] = pack2(a1.y, a1.y);
            am[6] = pack2(a1.z, a1.z); am[7] = pack2(a1.w, a1.w);
#pragma unroll
            for (int i = 0; i < 8; i++) {
                ffma2(acc2[i][0], am[i], b0.x);
                ffma2(acc2[i][1], am[i], b0.y);
                ffma2(acc2[i][2], am[i], b1.x);
                ffma2(acc2[i][3], am[i], b1.y);
            }
        }
        if (kt + 1 < KT) {
            int nbuf = (kt + 1) & 1;
            As[nbuf][a_k4 + 0][a_row] = a_frag.x;
            As[nbuf][a_k4 + 1][a_row] = a_frag.y;
            As[nbuf][a_k4 + 2][a_row] = a_frag.z;
            As[nbuf][a_k4 + 3][a_row] = a_frag.w;
            *(float4*)&Bs[nbuf][b_row][b_col] = b_frag;
            __syncthreads();
        }
    }

    // epilogue
#pragma unroll
    for (int i = 0; i < 8; i++) {
        int m = m0 + ((i < 4) ? (ty * 4 + i) : (64 + ty * 4 + (i - 4)));
        float bv = bias[m];
#pragma unroll
        for (int jh = 0; jh < 2; jh++) {
            int n = n0 + jh * 64 + tx * 4;
            float x0, x1, x2, x3;
            unpack2(acc2[i][jh * 2 + 0], x0, x1);
            unpack2(acc2[i][jh * 2 + 1], x2, x3);
            float4 r;
            r.x = x0 + bv; r.y = x1 + bv; r.z = x2 + bv; r.w = x3 + bv;
            if (res != nullptr) {
                float4 rv = *(const float4*)(res + (size_t)bz * M * N + (size_t)m * N + n);
                r.x += rv.x; r.y += rv.y; r.z += rv.z; r.w += rv.w;
            }
            *(float4*)(Cp + (size_t)m * N + n) = r;
        }
    }
}

// ---------------------------------------------------------------------------
// Kernel 3: flash attention, v2 (FIXED row-stride indexing).
// grid = (8 t-tiles, 128 heads), 128 threads, 2 blocks/SM.
// Thread owns one t-row. S row kept in REGISTERS as 32 packed f32x2 (64 j's).
// K/V tiles stored [c][j] (conflict-free writes, broadcast reads), Bc = 64,
// cp.async double-buffered. q in smem (self-read only, no sync needed).
// A tile row (64 floats) = 16 ulonglong2: row stride 16, j8 in [0,16).
// smem: Ks 2*16KB + Vs 2*16KB + Qs 32KB = 96KB  -> 2 blocks/SM (8 warps).
// ---------------------------------------------------------------------------
#define BC 64
#define ATTN_SMEM_FLOATS (2 * 4096 + 2 * 4096 + 64 * 128)
#define ATTN_SMEM_BYTES  (ATTN_SMEM_FLOATS * 4)

__global__ __launch_bounds__(128, 2) void attn_kernel(
    const float* __restrict__ qkv,
    float* __restrict__ hout)
{
    extern __shared__ float sm[];
    float* Ks = sm;                  // [2][64c][64j]
    float* Vs = sm + 2 * 4096;       // [2][64c][64j]
    float* Qs = sm + 4 * 4096;       // [64c][128t]

    int tt   = blockIdx.x;           // 0..7
    int head = blockIdx.y;           // 0..127
    int b  = head >> 3;
    int hl = head & 7;
    const float* base = qkv + ((size_t)b * 1536 + (size_t)hl * 192) * NN;
    const float* qg = base;
    const float* kg = base + 64 * NN;
    const float* vg = base + 128 * NN;

    int tid = threadIdx.x;
    int t = tt * 128 + tid;

    // q -> smem (scaled). Read back only by the same thread: no sync needed.
    for (int c = 0; c < CH; c++)
        Qs[c * 128 + tid] = qg[(size_t)c * NN + t] * 0.125f;

    // cp.async tile loader: [c][j] layout, 16B chunks, coalesced gmem reads
    int jj    = (tid & 15) * 4;      // j offset 0..60
    int chalf = tid >> 4;            // 0..7

    // prologue: tile 0 into buf 0
    {
#pragma unroll
        for (int p = 0; p < 8; p++) {
            int c = p * 8 + chalf;
            cp_async16(Ks + c * 64 + jj, kg + (size_t)c * NN + jj);
            cp_async16(Vs + c * 64 + jj, vg + (size_t)c * NN + jj);
        }
        cp_commit();
    }

    float o[CH];
#pragma unroll
    for (int c = 0; c < CH; c++) o[c] = 0.f;
    float mrun = -1e30f, lrun = 0.f;

    for (int st = 0; st < 16; ++st) {
        int buf = st & 1;
        cp_wait0();            // this tile's data landed (this thread's part)
        __syncthreads();       // all threads' parts landed; prev compute done

        if (st < 15) {         // prefetch next tile into the other buffer
            int s0n = (st + 1) * BC;
            float* Kb = Ks + (buf ^ 1) * 4096;
            float* Vb = Vs + (buf ^ 1) * 4096;
#pragma unroll
            for (int p = 0; p < 8; p++) {
                int c = p * 8 + chalf;
                cp_async16(Kb + c * 64 + jj, kg + (size_t)c * NN + s0n + jj);
                cp_async16(Vb + c * 64 + jj, vg + (size_t)c * NN + s0n + jj);
            }
            cp_commit();
        }

        // ---- S = q . K  (32 packed-pair accumulators = 64 scores) ----
        unsigned long long s2[32];
#pragma unroll
        for (int i = 0; i < 32; i++) s2[i] = 0ULL;

        const ulonglong2* K2 = (const ulonglong2*)(Ks + buf * 4096);
#pragma unroll
        for (int c = 0; c < CH; c++) {
            float qc = Qs[c * 128 + tid];
            unsigned long long qq = pack2(qc, qc);
#pragma unroll
            for (int j8 = 0; j8 < 16; j8++) {          // 16 x ulonglong2 = 64 j
                ulonglong2 kk = K2[c * 16 + j8];       // row stride 16
                ffma2(s2[2 * j8 + 0], qq, kk.x);
                ffma2(s2[2 * j8 + 1], qq, kk.y);
            }
        }

        // ---- online softmax ----
        float m0 = -1e30f, m1 = -1e30f, m2 = -1e30f, m3 = -1e30f;
#pragma unroll
        for (int i = 0; i < 32; i += 2) {
            float a, bb, cc, dd;
            unpack2(s2[i], a, bb);
            unpack2(s2[i + 1], cc, dd);
            m0 = fmaxf(m0, a); m1 = fmaxf(m1, bb);
            m2 = fmaxf(m2, cc); m3 = fmaxf(m3, dd);
        }
        float tmax = fmaxf(fmaxf(m0, m1), fmaxf(m2, m3));
        float mnew = fmaxf(mrun, tmax);
        float corr = __expf(mrun - mnew);
#pragma unroll
        for (int c = 0; c < CH; c++) o[c] *= corr;

        float l0 = 0.f, l1 = 0.f;
#pragma unroll
        for (int i = 0; i < 32; i++) {
            float a, bb;
            unpack2(s2[i], a, bb);
            a = __expf(a - mnew);
            bb = __expf(bb - mnew);
            l0 += a; l1 += bb;
            s2[i] = pack2(a, bb);
        }
        lrun = lrun * corr + l0 + l1;
        mrun = mnew;

        // ---- O += P . V^T ----
        const ulonglong2* V2 = (const ulonglong2*)(Vs + buf * 4096);
#pragma unroll
        for (int c = 0; c < CH; c++) {
            unsigned long long t0 = 0ULL, t1 = 0ULL;
#pragma unroll
            for (int j8 = 0; j8 < 16; j8++) {          // full 64-j row
                ulonglong2 vv = V2[c * 16 + j8];       // row stride 16
                ffma2(t0, s2[2 * j8 + 0], vv.x);
                ffma2(t1, s2[2 * j8 + 1], vv.y);
            }
            float a, bb, cc, dd;
            unpack2(t0, a, bb);
            unpack2(t1, cc, dd);
            o[c] += (a + bb) + (cc + dd);
        }
        // no trailing sync needed: next iteration's top sync (after cp_wait0)
        // orders this compute before any overwrite of this buffer.
    }

    float inv = 1.0f / lrun;
    float* hp = hout + ((size_t)b * CC + (size_t)hl * CH) * NN;
#pragma unroll
    for (int c = 0; c < CH; c++) hp[(size_t)c * NN + t] = o[c] * inv;
}

// ---------------------------------------------------------------------------
// Launch
// ---------------------------------------------------------------------------
extern "C" void kernel_launch(void* const* d_in, const int* in_sizes, int n_in,
                              void* d_out, int out_size)
{
    const float* x      = (const float*)d_in[0];
    const float* gamma  = (const float*)d_in[1];
    const float* beta   = (const float*)d_in[2];
    const float* w_qkv  = (const float*)d_in[3];
    const float* b_qkv  = (const float*)d_in[4];
    const float* w_proj = (const float*)d_in[5];
    const float* b_proj = (const float*)d_in[6];
    float* out = (float*)d_out;

    float *xn, *qkv, *h;
    cudaGetSymbolAddress((void**)&xn,  g_xn);
    cudaGetSymbolAddress((void**)&qkv, g_qkv);
    cudaGetSymbolAddress((void**)&h,   g_h);

    // 1. GroupNorm
    groupnorm_kernel<<<BB * GROUPS, 256>>>(x, gamma, beta, xn);

    // 2. QKV projection: (1536,512) @ (16,512,1024) + bias
    gemm_kernel<<<dim3(NN / 128, (3 * CC) / 128, BB), 256>>>(
        w_qkv, xn, b_qkv, nullptr, qkv, 3 * CC, CC, NN);

    // 3. Attention
    cudaFuncSetAttribute(attn_kernel, cudaFuncAttributeMaxDynamicSharedMemorySize,
                         ATTN_SMEM_BYTES);
    attn_kernel<<<dim3(8, BB * HEADS), 128, ATTN_SMEM_BYTES>>>(qkv, h);

    // 4. Output projection + bias + residual
    gemm_kernel<<<dim3(NN / 128, CC / 128, BB), 256>>>(
        w_proj, h, b_proj, x, out, CC, CC, NN);
}

// round 14
// speedup vs baseline: 1.0023x; 1.0004x over previous
#include <cuda_runtime.h>
#include <cstddef>
#include <cstdint>

// Problem constants
#define BB     16
#define CC     512
#define NN     1024      // H*W = 32*32
#define GROUPS 32
#define CPG    16        // channels per group
#define HEADS  8
#define CH     64        // channels per head

// Scratch (device globals — no allocation allowed)
__device__ float g_xn [(size_t)BB * CC * NN];        // 32 MB  groupnorm output
__device__ float g_qkv[(size_t)BB * 3 * CC * NN];    // 96 MB  qkv projection
__device__ float g_h  [(size_t)BB * CC * NN];        // 32 MB  attention output

// ---------------------------------------------------------------------------
// f32x2 packed-FMA helpers (sm_103a FFMA2 — only reachable via PTX)
// ---------------------------------------------------------------------------
__device__ __forceinline__ unsigned long long pack2(float lo, float hi) {
    unsigned long long r;
    asm("mov.b64 %0, {%1, %2};" : "=l"(r) : "f"(lo), "f"(hi));
    return r;
}
__device__ __forceinline__ void unpack2(unsigned long long v, float& lo, float& hi) {
    asm("mov.b64 {%0, %1}, %2;" : "=f"(lo), "=f"(hi) : "l"(v));
}
__device__ __forceinline__ void ffma2(unsigned long long& d,
                                      unsigned long long a,
                                      unsigned long long b) {
    asm("fma.rn.f32x2 %0, %1, %2, %0;" : "+l"(d) : "l"(a), "l"(b));
}

// cp.async helpers
__device__ __forceinline__ void cp_async16(void* smem_dst, const void* gsrc) {
    uint32_t sa = (uint32_t)__cvta_generic_to_shared(smem_dst);
    asm volatile("cp.async.cg.shared.global [%0], [%1], 16;" :: "r"(sa), "l"(gsrc));
}
__device__ __forceinline__ void cp_commit() {
    asm volatile("cp.async.commit_group;");
}
__device__ __forceinline__ void cp_wait0() {
    asm volatile("cp.async.wait_group 0;" ::: "memory");
}

// ---------------------------------------------------------------------------
// Kernel 1: GroupNorm.  One block per (batch, group). 16 ch * 1024 = 16384 el.
// ---------------------------------------------------------------------------
__global__ __launch_bounds__(256) void groupnorm_kernel(
    const float* __restrict__ x,
    const float* __restrict__ gamma,
    const float* __restrict__ beta,
    float* __restrict__ out)
{
    int bg = blockIdx.x;                 // 0..511
    int b  = bg / GROUPS;
    int g  = bg % GROUPS;
    const float* xp = x   + ((size_t)b * CC + (size_t)g * CPG) * NN;
    float*       op = out + ((size_t)b * CC + (size_t)g * CPG) * NN;
    int tid = threadIdx.x;

    float4 v[16];
    float s = 0.f, s2 = 0.f;
#pragma unroll
    for (int i = 0; i < 16; i++) {
        v[i] = ((const float4*)xp)[tid + i * 256];
        s  += v[i].x + v[i].y + v[i].z + v[i].w;
        s2 += v[i].x * v[i].x + v[i].y * v[i].y + v[i].z * v[i].z + v[i].w * v[i].w;
    }

    __shared__ float rs[256], rq[256];
    rs[tid] = s; rq[tid] = s2;
    __syncthreads();
    for (int off = 128; off > 0; off >>= 1) {
        if (tid < off) { rs[tid] += rs[tid + off]; rq[tid] += rq[tid + off]; }
        __syncthreads();
    }
    float mean = rs[0] * (1.0f / 16384.0f);
    float var  = rq[0] * (1.0f / 16384.0f) - mean * mean;
    float rstd = rsqrtf(var + 1e-5f);

#pragma unroll
    for (int i = 0; i < 16; i++) {
        int idx4 = tid + i * 256;
        int c_local = (idx4 * 4) >> 10;
        float gm = gamma[g * CPG + c_local] * rstd;
        float bt = beta [g * CPG + c_local] - mean * gm;
        float4 o;
        o.x = v[i].x * gm + bt;
        o.y = v[i].y * gm + bt;
        o.z = v[i].z * gm + bt;
        o.w = v[i].w * gm + bt;
        ((float4*)op)[idx4] = o;
    }
}

// ---------------------------------------------------------------------------
// Kernel 2/4: batched SGEMM with packed f32x2 microkernel.
// C[b] = A(MxK) @ B[b](KxN) + bias (+ residual)
// 128x128 tile, Ktile=8, double-buffered smem, 8x8 microtile (as 8x4 f32x2).
// ---------------------------------------------------------------------------
__global__ __launch_bounds__(256) void gemm_kernel(
    const float* __restrict__ A,
    const float* __restrict__ Bm,
    const float* __restrict__ bias,
    const float* __restrict__ res,
    float* __restrict__ Cm,
    int M, int K, int N)
{
    __shared__ __align__(16) float As[2][8][128];
    __shared__ __align__(16) float Bs[2][8][128];

    int bz = blockIdx.z;
    const float* Bp = Bm + (size_t)bz * K * N;
    float*       Cp = Cm + (size_t)bz * M * N;

    int tid = threadIdx.x;
    int m0 = blockIdx.y * 128;
    int n0 = blockIdx.x * 128;

    int a_row = tid >> 1;
    int a_k4  = (tid & 1) * 4;
    int b_row = tid >> 5;
    int b_col = (tid & 31) * 4;

    float4 a_frag = *(const float4*)(A  + (size_t)(m0 + a_row) * K + a_k4);
    float4 b_frag = *(const float4*)(Bp + (size_t)b_row * N + n0 + b_col);
    As[0][a_k4 + 0][a_row] = a_frag.x;
    As[0][a_k4 + 1][a_row] = a_frag.y;
    As[0][a_k4 + 2][a_row] = a_frag.z;
    As[0][a_k4 + 3][a_row] = a_frag.w;
    *(float4*)&Bs[0][b_row][b_col] = b_frag;
    __syncthreads();

    unsigned long long acc2[8][4];
#pragma unroll
    for (int i = 0; i < 8; i++)
#pragma unroll
        for (int j = 0; j < 4; j++) acc2[i][j] = 0ULL;

    int tx = tid & 15;   // n
    int ty = tid >> 4;   // m
    int KT = K >> 3;

    for (int kt = 0; kt < KT; ++kt) {
        int buf = kt & 1;
        if (kt + 1 < KT) {
            int kg = (kt + 1) * 8;
            a_frag = *(const float4*)(A  + (size_t)(m0 + a_row) * K + kg + a_k4);
            b_frag = *(const float4*)(Bp + (size_t)(kg + b_row) * N + n0 + b_col);
        }
#pragma unroll
        for (int k = 0; k < 8; k++) {
            float4 a0 = *(const float4*)&As[buf][k][ty * 4];
            float4 a1 = *(const float4*)&As[buf][k][ty * 4 + 64];
            ulonglong2 b0 = *(const ulonglong2*)&Bs[buf][k][tx * 4];
            ulonglong2 b1 = *(const ulonglong2*)&Bs[buf][k][tx * 4 + 64];
            unsigned long long am[8];
            am[0] = pack2(a0.x, a0.x); am[1] = pack2(a0.y, a0.y);
            am[2] = pack2(a0.z, a0.z); am[3] = pack2(a0.w, a0.w);
            am[4] = pack2(a1.x, a1.x); am[5] = pack2(a1.y, a1.y);
            am[6] = pack2(a1.z, a1.z); am[7] = pack2(a1.w, a1.w);
#pragma unroll
            for (int i = 0; i < 8; i++) {
                ffma2(acc2[i][0], am[i], b0.x);
                ffma2(acc2[i][1], am[i], b0.y);
                ffma2(acc2[i][2], am[i], b1.x);
                ffma2(acc2[i][3], am[i], b1.y);
            }
        }
        if (kt + 1 < KT) {
            int nbuf = (kt + 1) & 1;
            As[nbuf][a_k4 + 0][a_row] = a_frag.x;
            As[nbuf][a_k4 + 1][a_row] = a_frag.y;
            As[nbuf][a_k4 + 2][a_row] = a_frag.z;
            As[nbuf][a_k4 + 3][a_row] = a_frag.w;
            *(float4*)&Bs[nbuf][b_row][b_col] = b_frag;
            __syncthreads();
        }
    }

    // epilogue
#pragma unroll
    for (int i = 0; i < 8; i++) {
        int m = m0 + ((i < 4) ? (ty * 4 + i) : (64 + ty * 4 + (i - 4)));
        float bv = bias[m];
#pragma unroll
        for (int jh = 0; jh < 2; jh++) {
            int n = n0 + jh * 64 + tx * 4;
            float x0, x1, x2, x3;
            unpack2(acc2[i][jh * 2 + 0], x0, x1);
            unpack2(acc2[i][jh * 2 + 1], x2, x3);
            float4 r;
            r.x = x0 + bv; r.y = x1 + bv; r.z = x2 + bv; r.w = x3 + bv;
            if (res != nullptr) {
                float4 rv = *(const float4*)(res + (size_t)bz * M * N + (size_t)m * N + n);
                r.x += rv.x; r.y += rv.y; r.z += rv.z; r.w += rv.w;
            }
            *(float4*)(Cp + (size_t)m * N + n) = r;
        }
    }
}

// ---------------------------------------------------------------------------
// Kernel 3: flash attention, v2 (FIXED row-stride indexing).
// grid = (8 t-tiles, 128 heads), 128 threads, 2 blocks/SM.
// Thread owns one t-row. S row kept in REGISTERS as 32 packed f32x2 (64 j's).
// K/V tiles stored [c][j] (conflict-free writes, broadcast reads), Bc = 64,
// cp.async double-buffered. q in smem (self-read only, no sync needed).
// A tile row (64 floats) = 16 ulonglong2: row stride 16, j8 in [0,16).
// smem: Ks 2*16KB + Vs 2*16KB + Qs 32KB = 96KB  -> 2 blocks/SM (8 warps).
// ---------------------------------------------------------------------------
#define BC 64
#define ATTN_SMEM_FLOATS (2 * 4096 + 2 * 4096 + 64 * 128)
#define ATTN_SMEM_BYTES  (ATTN_SMEM_FLOATS * 4)

__global__ __launch_bounds__(128, 2) void attn_kernel(
    const float* __restrict__ qkv,
    float* __restrict__ hout)
{
    extern __shared__ float sm[];
    float* Ks = sm;                  // [2][64c][64j]
    float* Vs = sm + 2 * 4096;       // [2][64c][64j]
    float* Qs = sm + 4 * 4096;       // [64c][128t]

    int tt   = blockIdx.x;           // 0..7
    int head = blockIdx.y;           // 0..127
    int b  = head >> 3;
    int hl = head & 7;
    const float* base = qkv + ((size_t)b * 1536 + (size_t)hl * 192) * NN;
    const float* qg = base;
    const float* kg = base + 64 * NN;
    const float* vg = base + 128 * NN;

    int tid = threadIdx.x;
    int t = tt * 128 + tid;

    // q -> smem (scaled). Read back only by the same thread: no sync needed.
    for (int c = 0; c < CH; c++)
        Qs[c * 128 + tid] = qg[(size_t)c * NN + t] * 0.125f;

    // cp.async tile loader: [c][j] layout, 16B chunks, coalesced gmem reads
    int jj    = (tid & 15) * 4;      // j offset 0..60
    int chalf = tid >> 4;            // 0..7

    // prologue: tile 0 into buf 0
    {
#pragma unroll
        for (int p = 0; p < 8; p++) {
            int c = p * 8 + chalf;
            cp_async16(Ks + c * 64 + jj, kg + (size_t)c * NN + jj);
            cp_async16(Vs + c * 64 + jj, vg + (size_t)c * NN + jj);
        }
        cp_commit();
    }

    float o[CH];
#pragma unroll
    for (int c = 0; c < CH; c++) o[c] = 0.f;
    float mrun = -1e30f, lrun = 0.f;

    for (int st = 0; st < 16; ++st) {
        int buf = st & 1;
        cp_wait0();            // this tile's data landed (this thread's part)
        __syncthreads();       // all threads' parts landed; prev compute done

        if (st < 15) {         // prefetch next tile into the other buffer
            int s0n = (st + 1) * BC;
            float* Kb = Ks + (buf ^ 1) * 4096;
            float* Vb = Vs + (buf ^ 1) * 4096;
#pragma unroll
            for (int p = 0; p < 8; p++) {
                int c = p * 8 + chalf;
                cp_async16(Kb + c * 64 + jj, kg + (size_t)c * NN + s0n + jj);
                cp_async16(Vb + c * 64 + jj, vg + (size_t)c * NN + s0n + jj);
            }
            cp_commit();
        }

        // ---- S = q . K  (32 packed-pair accumulators = 64 scores) ----
        unsigned long long s2[32];
#pragma unroll
        for (int i = 0; i < 32; i++) s2[i] = 0ULL;

        const ulonglong2* K2 = (const ulonglong2*)(Ks + buf * 4096);
#pragma unroll
        for (int c = 0; c < CH; c++) {
            float qc = Qs[c * 128 + tid];
            unsigned long long qq = pack2(qc, qc);
#pragma unroll
            for (int j8 = 0; j8 < 16; j8++) {          // 16 x ulonglong2 = 64 j
                ulonglong2 kk = K2[c * 16 + j8];       // row stride 16
                ffma2(s2[2 * j8 + 0], qq, kk.x);
                ffma2(s2[2 * j8 + 1], qq, kk.y);
            }
        }

        // ---- online softmax ----
        float m0 = -1e30f, m1 = -1e30f, m2 = -1e30f, m3 = -1e30f;
#pragma unroll
        for (int i = 0; i < 32; i += 2) {
            float a, bb, cc, dd;
            unpack2(s2[i], a, bb);
            unpack2(s2[i + 1], cc, dd);
            m0 = fmaxf(m0, a); m1 = fmaxf(m1, bb);
            m2 = fmaxf(m2, cc); m3 = fmaxf(m3, dd);
        }
        float tmax = fmaxf(fmaxf(m0, m1), fmaxf(m2, m3));
        float mnew = fmaxf(mrun, tmax);
        float corr = __expf(mrun - mnew);
#pragma unroll
        for (int c = 0; c < CH; c++) o[c] *= corr;

        float l0 = 0.f, l1 = 0.f;
#pragma unroll
        for (int i = 0; i < 32; i++) {
            float a, bb;
            unpack2(s2[i], a, bb);
            a = __expf(a - mnew);
            bb = __expf(bb - mnew);
            l0 += a; l1 += bb;
            s2[i] = pack2(a, bb);
        }
        lrun = lrun * corr + l0 + l1;
        mrun = mnew;

        // ---- O += P . V^T ----
        const ulonglong2* V2 = (const ulonglong2*)(Vs + buf * 4096);
#pragma unroll
        for (int c = 0; c < CH; c++) {
            unsigned long long t0 = 0ULL, t1 = 0ULL;
#pragma unroll
            for (int j8 = 0; j8 < 16; j8++) {          // full 64-j row
                ulonglong2 vv = V2[c * 16 + j8];       // row stride 16
                ffma2(t0, s2[2 * j8 + 0], vv.x);
                ffma2(t1, s2[2 * j8 + 1], vv.y);
            }
            float a, bb, cc, dd;
            unpack2(t0, a, bb);
            unpack2(t1, cc, dd);
            o[c] += (a + bb) + (cc + dd);
        }
        // no trailing sync needed: next iteration's top sync (after cp_wait0)
        // orders this compute before any overwrite of this buffer.
    }

    float inv = 1.0f / lrun;
    float* hp = hout + ((size_t)b * CC + (size_t)hl * CH) * NN;
#pragma unroll
    for (int c = 0; c < CH; c++) hp[(size_t)c * NN + t] = o[c] * inv;
}

// ---------------------------------------------------------------------------
// Launch
// ---------------------------------------------------------------------------
extern "C" void kernel_launch(void* const* d_in, const int* in_sizes, int n_in,
                              void* d_out, int out_size)
{
    const float* x      = (const float*)d_in[0];
    const float* gamma  = (const float*)d_in[1];
    const float* beta   = (const float*)d_in[2];
    const float* w_qkv  = (const float*)d_in[3];
    const float* b_qkv  = (const float*)d_in[4];
    const float* w_proj = (const float*)d_in[5];
    const float* b_proj = (const float*)d_in[6];
    float* out = (float*)d_out;

    float *xn, *qkv, *h;
    cudaGetSymbolAddress((void**)&xn,  g_xn);
    cudaGetSymbolAddress((void**)&qkv, g_qkv);
    cudaGetSymbolAddress((void**)&h,   g_h);

    // 1. GroupNorm
    groupnorm_kernel<<<BB * GROUPS, 256>>>(x, gamma, beta, xn);

    // 2. QKV projection: (1536,512) @ (16,512,1024) + bias
    gemm_kernel<<<dim3(NN / 128, (3 * CC) / 128, BB), 256>>>(
        w_qkv, xn, b_qkv, nullptr, qkv, 3 * CC, CC, NN);

    // 3. Attention
    cudaFuncSetAttribute(attn_kernel, cudaFuncAttributeMaxDynamicSharedMemorySize,
                         ATTN_SMEM_BYTES);
    attn_kernel<<<dim3(8, BB * HEADS), 128, ATTN_SMEM_BYTES>>>(qkv, h);

    // 4. Output projection + bias + residual
    gemm_kernel<<<dim3(NN / 128, CC / 128, BB), 256>>>(
        w_proj, h, b_proj, x, out, CC, CC, NN);
}